// round 13
// baseline (speedup 1.0000x reference)
#include <cuda_runtime.h>
#include <stdint.h>
#include <cooperative_groups.h>
namespace cg = cooperative_groups;

#define BATCH 16
#define WPR 16
#define WPI 8192
#define NPIX 4194304
#define NBLK 2048
#define ROWS_CTA 128
#define NGRP 32
#define SSTRIDE 18
#define SBUF (ROWS_CTA*SSTRIDE)
#define PCB 128

// ---------------- scratch (no allocation allowed) ----------------
__device__ uint32_t g_pred[BATCH*WPI];
__device__ uint32_t g_true[BATCH*WPI];
__device__ uint32_t g_ps[BATCH*WPI];
__device__ uint32_t g_ts[BATCH*WPI];
__device__ float    g_part[4*NBLK];
__device__ int      g_icnt[BATCH];
__device__ int      g_pcnt[BATCH];
__device__ int      g_tcnt[BATCH];
__device__ int      g_ctr;

// ---------------- PTX helpers ------------------------------------
__device__ __forceinline__ uint32_t smem_u32(const void* p){
    uint32_t a;
    asm("{ .reg .u64 t; cvta.to.shared.u64 t, %1; cvt.u32.u64 %0, t; }"
        : "=r"(a) : "l"(p));
    return a;
}

#define MBAR_INIT(addr, cnt) \
    asm volatile("mbarrier.init.shared.b64 [%0], %1;" :: "r"(addr), "r"(cnt) : "memory")

// release-arrive on the same-offset barrier in a peer CTA
#define ARRIVE_NBR(bar_u32, trank) \
    asm volatile("{\n\t.reg .b32 ra;\n\t" \
        "mapa.shared::cluster.u32 ra, %0, %1;\n\t" \
        "mbarrier.arrive.release.cluster.shared::cluster.b64 _, [ra];\n\t}" \
        :: "r"(bar_u32), "r"(trank) : "memory")

// acquire-wait (cluster scope) on local barrier, phase parity
#define WAIT_PAR(bar_u32, par) do{ \
    asm volatile("{\n\t.reg .pred P;\n\t" \
        "WL_%=:\n\t" \
        "mbarrier.try_wait.parity.acquire.cluster.shared::cta.b64 P, [%0], %1, 0x989680;\n\t" \
        "@P bra.uni WD_%=;\n\t" \
        "bra.uni WL_%=;\n\t" \
        "WD_%=:\n\t}" \
        :: "r"(bar_u32), "r"(par) : "memory"); }while(0)

// plain store into peer CTA smem at same offset
#define ST_PEER(addr_u32, trank, val) \
    asm volatile("{\n\t.reg .b32 ra;\n\t" \
        "mapa.shared::cluster.u32 ra, %0, %1;\n\t" \
        "st.shared::cluster.u32 [ra], %2;\n\t}" \
        :: "r"(addr_u32), "r"(trank), "r"(val) : "memory")

// ---------------- kernel A: binarize + dice/focal partials -------
__global__ __launch_bounds__(256, 7) void kA(const float* __restrict__ logits,
                                             const int*   __restrict__ tr){
    int tid = threadIdx.x;
    int gt  = blockIdx.x*256 + tid;
    int i8  = gt*8;
    int b   = i8 >> 18;
    int rem = i8 & ((1<<18)-1);

    const float4* F = (const float4*)logits;
    size_t q0 = (((size_t)(2*b) << 18) + rem) >> 2;
    size_t q1 = q0 + (1u << 16);
    const int4* T4 = (const int4*)tr;
    size_t qt = ((size_t)i8) >> 2;

    float4 A0 = F[q0], A1 = F[q0+1];
    float4 B0 = F[q1], B1 = F[q1+1];
    int4   t0 = T4[qt], t1 = T4[qt+1];

    float L0[8] = {A0.x,A0.y,A0.z,A0.w,A1.x,A1.y,A1.z,A1.w};
    float L1[8] = {B0.x,B0.y,B0.z,B0.w,B1.x,B1.y,B1.z,B1.w};
    int   TT[8] = {t0.x,t0.y,t0.z,t0.w,t1.x,t1.y,t1.z,t1.w};

    unsigned pm = 0, tm = 0;
    float s1 = 0.f, s2 = 0.f, s3 = 0.f, s4 = 0.f;
    #pragma unroll
    for (int j = 0; j < 8; j++){
        float d = L1[j] - L0[j];
        bool pd = d > 0.f;
        bool tp = TT[j] > 0;
        pm |= (unsigned)pd << j;
        tm |= (unsigned)tp << j;
        float ad = fabsf(d);
        float e  = __expf(-ad);
        float pb = __fdividef(1.f, 1.f + e);
        float lg = -__logf(pb);
        float p1 = pd ? pb : 1.f - pb;
        float ce = (tp == pd) ? lg : (ad + lg);
        float pt = tp ? p1 : 1.f - p1;
        float om = 1.f - pt;
        s4 += 0.25f * om * om * ce;
        s2 += p1;
        s1 += tp ? p1 : 0.f;
        s3 += tp ? 1.f : 0.f;
    }
    ((uint8_t*)g_pred)[gt] = (uint8_t)pm;
    ((uint8_t*)g_true)[gt] = (uint8_t)tm;

    __shared__ float red[8*4];
    int lane = tid & 31, wid = tid >> 5;
    float vals[4] = {s1, s2, s3, s4};
    #pragma unroll
    for (int v = 0; v < 4; v++){
        float x = vals[v];
        #pragma unroll
        for (int o = 16; o; o >>= 1) x += __shfl_down_sync(0xffffffffu, x, o);
        if (lane == 0) red[wid*4 + v] = x;
    }
    __syncthreads();
    if (wid == 0 && lane < 4){
        float s = 0.f;
        #pragma unroll
        for (int w = 0; w < 8; w++) s += red[w*4 + lane];
        g_part[lane*NBLK + blockIdx.x] = s;
    }
}

// ---------------- kernel B: activity-gated Zhang-Suen ------------
// Round-5 dataflow (sub0: S0->S1, sub1: S1->S0, 2-subiter gating window),
// cluster.sync replaced by neighbor-pair mbarriers + pushed exit flags.
template<int SUB>
__device__ __forceinline__ bool subiter(
    const uint32_t* __restrict__ src, uint32_t* __restrict__ dst,
    const uint32_t* upS, const uint32_t* dnS,
    uint32_t* __restrict__ act,
    const uint32_t* __restrict__ mb_up, const uint32_t* __restrict__ mb_dn,
    uint32_t* up_mbdn, uint32_t* dn_mbup, int mbw,
    int g, int w, uint32_t wm, int tid)
{
    uint32_t am1 = (g == 0)      ? (mb_up[0] | mb_up[1] | mb_up[2])
                                 : (act[g-1] | act[NGRP + g-1]);
    uint32_t a0  = act[g] | act[NGRP + g];
    uint32_t ap1 = (g == NGRP-1) ? (mb_dn[0] | mb_dn[1] | mb_dn[2])
                                 : (act[g+1] | act[NGRP + g+1]);
    uint32_t actv = (am1 | a0 | ap1) & wm;
    __syncthreads();

    bool changed = false;
    if (actv){
        uint32_t C[6], E[6], Wm[6];
        #pragma unroll
        for (int i = 0; i < 6; i++){
            int r = 4*g - 1 + i;
            uint32_t c, l, rr;
            if (r >= 0 && r < ROWS_CTA){
                const uint32_t* row = src + r*SSTRIDE;
                c = row[w]; l = (w > 0) ? row[w-1] : 0u; rr = (w < 15) ? row[w+1] : 0u;
            } else if (r < 0){
                if (upS){
                    const uint32_t* row = upS + (ROWS_CTA-1)*SSTRIDE;
                    c = row[w]; l = (w > 0) ? row[w-1] : 0u; rr = (w < 15) ? row[w+1] : 0u;
                } else { c = l = rr = 0u; }
            } else {
                if (dnS){
                    const uint32_t* row = dnS;
                    c = row[w]; l = (w > 0) ? row[w-1] : 0u; rr = (w < 15) ? row[w+1] : 0u;
                } else { c = l = rr = 0u; }
            }
            C[i]  = c;
            E[i]  = __funnelshift_r(c, rr, 1);
            Wm[i] = __funnelshift_l(l, c, 1);
        }
        #pragma unroll
        for (int k = 0; k < 4; k++){
            int i = k + 1;
            uint32_t cC = C[i];
            uint32_t p2 = C[i-1], p3 = E[i-1], p9 = Wm[i-1];
            uint32_t p4 = E[i],   p8 = Wm[i];
            uint32_t p6 = C[i+1], p5 = E[i+1], p7 = Wm[i+1];

            uint32_t sa = p2 ^ p3 ^ p4, ca = (p2 & p3) | (p4 & (p2 ^ p3));
            uint32_t sb = p5 ^ p6 ^ p7, cb = (p5 & p6) | (p7 & (p5 ^ p6));
            uint32_t sc = p8 ^ p9,      cc = p8 & p9;
            uint32_t S0v = sa ^ sb ^ sc, cd = (sa & sb) | (sc & (sa ^ sb));
            uint32_t t1v = ca ^ cb ^ cc, c1a = (ca & cb) | (cc & (ca ^ cb));
            uint32_t S1v = t1v ^ cd,     c1b = t1v & cd;
            uint32_t S2v = c1a ^ c1b,    S3v = c1a & c1b;
            uint32_t cond1 = (S1v | S2v | S3v) & ~(S3v | (S2v & S1v & S0v));

            uint32_t t0 = ~p2 & p3;
            uint32_t t1_ = ~p3 & p4;
            uint32_t t2 = ~p4 & p5;
            uint32_t t3 = ~p5 & p6;
            uint32_t t4 = ~p6 & p7;
            uint32_t t5 = ~p7 & p8;
            uint32_t t6 = ~p8 & p9;
            uint32_t t7 = ~p9 & p2;
            uint32_t onep = t0, two = 0;
            two |= onep & t1_; onep |= t1_;
            two |= onep & t2;  onep |= t2;
            two |= onep & t3;  onep |= t3;
            two |= onep & t4;  onep |= t4;
            two |= onep & t5;  onep |= t5;
            two |= onep & t6;  onep |= t6;
            two |= onep & t7;  onep |= t7;
            uint32_t condA = onep & ~two;

            uint32_t c3m, c4m;
            if (SUB == 0){ c3m = ~(p2 & p4 & p6); c4m = ~(p4 & p6 & p8); }
            else         { c3m = ~(p2 & p4 & p8); c4m = ~(p2 & p6 & p8); }

            uint32_t remv = cC & cond1 & condA & c3m & c4m;
            dst[(4*g + k)*SSTRIDE + w] = cC & ~remv;
            changed = changed || (remv != 0u);
        }
    }

    unsigned bal = __ballot_sync(0xffffffffu, changed);
    int lane = tid & 31;
    if (lane == 0 || lane == 16){
        uint32_t v = (lane == 0) ? (bal & 0xFFFFu) : (bal >> 16);
        act[SUB*NGRP + g] = v;
        if (g == 0       && up_mbdn) up_mbdn[mbw] = v;
        if (g == NGRP-1  && dn_mbup) dn_mbup[mbw] = v;
    }
    return changed;
}

__global__ void __cluster_dims__(4,1,1) __launch_bounds__(512) kB(){
    __shared__ uint32_t S[2][SBUF];
    __shared__ uint32_t act[2*NGRP];
    __shared__ uint32_t mb_up[3], mb_dn[3];
    __shared__ uint32_t flg[4][4];          // [iter&3][rank], pushed by all CTAs
    __shared__ uint64_t mbar[2];            // neighbor barriers (sub0, sub1)

    cg::cluster_group cl = cg::this_cluster();
    unsigned rank = cl.block_rank();
    int unit = blockIdx.x >> 2;
    int img  = unit >> 1;
    int sel  = unit & 1;
    const uint32_t* srcg = (sel ? g_true : g_pred) + img*WPI + rank*2048;
    uint32_t*       dstg = (sel ? g_ts   : g_ps)   + img*WPI + rank*2048;

    int tid = threadIdx.x;
    int g = tid >> 4, w = tid & 15;
    bool hasUp = rank > 0, hasDn = rank < 3;
    int nnb = (int)hasUp + (int)hasDn;
    int upR = (int)rank - 1, dnR = (int)rank + 1;

    #pragma unroll
    for (int it = 0; it < 4; it++){
        int idx = tid + it*512;
        S[0][(idx>>4)*SSTRIDE + (idx&15)] = srcg[idx];
    }
    if (tid < NGRP){ act[tid] = 0xFFFFu; act[NGRP + tid] = 0xFFFFu; }
    uint32_t bar0 = smem_u32(&mbar[0]);
    uint32_t bar1 = smem_u32(&mbar[1]);
    uint32_t flg_base = smem_u32(&flg[0][0]);
    if (tid == 0){
        uint32_t u = hasUp ? 0xFFFFu : 0u;
        uint32_t d = hasDn ? 0xFFFFu : 0u;
        mb_up[0] = mb_up[1] = mb_up[2] = u;
        mb_dn[0] = mb_dn[1] = mb_dn[2] = d;
        // seed flags: iterations -2,-1 (slots 2,3) = changed
        #pragma unroll
        for (int r = 0; r < 4; r++){
            flg[0][r] = 0u; flg[1][r] = 0u; flg[2][r] = 1u; flg[3][r] = 1u;
        }
        MBAR_INIT(bar0, nnb);
        MBAR_INIT(bar1, nnb);
    }

    uint32_t* upS = hasUp ? cl.map_shared_rank(&S[0][0], rank-1) : (uint32_t*)0;
    uint32_t* dnS = hasDn ? cl.map_shared_rank(&S[0][0], rank+1) : (uint32_t*)0;
    uint32_t* up_mbdn = hasUp ? cl.map_shared_rank(&mb_dn[0], rank-1) : (uint32_t*)0;
    uint32_t* dn_mbup = hasDn ? cl.map_shared_rank(&mb_up[0], rank+1) : (uint32_t*)0;

    cl.sync();   // inputs + barrier/flag init visible cluster-wide

    uint32_t wm = (w == 0) ? 0x3u : (7u << (w - 1));
    int mbw = 0;
    for (int k = 0; ; k++){
        // exit check on 2-iteration-stale flags (identical at every CTA)
        int sl = (k + 2) & 3;   // == (k-2)&3
        uint32_t anyc = flg[sl][0] | flg[sl][1] | flg[sl][2] | flg[sl][3];
        if (!anyc) break;
        int par = k & 1;

        // ---- subiter 0: S0 (+peer S0 halo) -> S1 ----
        bool ch0 = subiter<0>(&S[0][0], &S[1][0],
                              upS, dnS,
                              act, mb_up, mb_dn, up_mbdn, dn_mbup, mbw,
                              g, w, wm, tid);
        mbw = (mbw == 2) ? 0 : mbw + 1;
        __syncthreads();                         // all CTA writes done
        if (tid == 0){
            if (hasUp) ARRIVE_NBR(bar0, upR);
            if (hasDn) ARRIVE_NBR(bar0, dnR);
        }
        WAIT_PAR(bar0, par);                     // neighbors finished sub0

        // ---- subiter 1: S1 (+peer S1 halo) -> S0 ----
        bool ch1 = subiter<1>(&S[1][0], &S[0][0],
                              upS ? upS + SBUF : (uint32_t*)0,
                              dnS ? dnS + SBUF : (uint32_t*)0,
                              act, mb_up, mb_dn, up_mbdn, dn_mbup, mbw,
                              g, w, wm, tid);
        mbw = (mbw == 2) ? 0 : mbw + 1;
        int myflag = __syncthreads_or((int)(ch0 || ch1));
        if (tid == 0){
            uint32_t v = myflag ? 1u : 0u;
            uint32_t fa = flg_base + (uint32_t)(((k & 3)*4 + (int)rank)*4);
            flg[k & 3][rank] = v;                // local
            #pragma unroll
            for (int t = 0; t < 4; t++){
                if (t != (int)rank) ST_PEER(fa, t, v);
            }
            if (hasUp) ARRIVE_NBR(bar1, upR);
            if (hasDn) ARRIVE_NBR(bar1, dnR);
        }
        WAIT_PAR(bar1, par);                     // neighbors finished sub1 (+flags)
    }

    cl.sync();   // unanimous exit; protect smem until peers done
    #pragma unroll
    for (int it = 0; it < 4; it++){
        int idx = tid + it*512;
        dstg[idx] = S[0][(idx>>4)*SSTRIDE + (idx&15)];
    }
}

// ---------------- kernel CD: parallel popcounts + final combine --
__global__ __launch_bounds__(256) void kCD(float* __restrict__ out){
    int tid = threadIdx.x;
    if (blockIdx.x < PCB){
        int b     = blockIdx.x >> 3;
        int slice = blockIdx.x & 7;
        const uint4* A  = (const uint4*)(g_ps + b*WPI + slice*1024);
        const uint4* Cc = (const uint4*)(g_ts + b*WPI + slice*1024);
        uint4 a = A[tid], c = Cc[tid];
        int inter = __popc(a.x & c.x) + __popc(a.y & c.y) + __popc(a.z & c.z) + __popc(a.w & c.w);
        int sp    = __popc(a.x) + __popc(a.y) + __popc(a.z) + __popc(a.w);
        int st    = __popc(c.x) + __popc(c.y) + __popc(c.z) + __popc(c.w);

        __shared__ int red[8*3];
        int lane = tid & 31, wid = tid >> 5;
        int v3[3] = {inter, sp, st};
        #pragma unroll
        for (int v = 0; v < 3; v++){
            int x = v3[v];
            #pragma unroll
            for (int o = 16; o; o >>= 1) x += __shfl_down_sync(0xffffffffu, x, o);
            if (lane == 0) red[wid*3 + v] = x;
        }
        __syncthreads();
        if (tid == 0){
            int ti = 0, tp = 0, tt = 0;
            #pragma unroll
            for (int w = 0; w < 8; w++){ ti += red[w*3]; tp += red[w*3+1]; tt += red[w*3+2]; }
            atomicAdd(&g_icnt[b], ti);
            atomicAdd(&g_pcnt[b], tp);
            atomicAdd(&g_tcnt[b], tt);
            __threadfence();
            atomicAdd(&g_ctr, 1);
        }
    } else {
        __shared__ float red[8*4];
        int lane = tid & 31, wid = tid >> 5;
        #pragma unroll
        for (int v = 0; v < 4; v++){
            const float4* P = (const float4*)(g_part + v*NBLK);
            float4 a = P[tid], b = P[tid + 256];
            float x = ((a.x + a.y) + (a.z + a.w)) + ((b.x + b.y) + (b.z + b.w));
            #pragma unroll
            for (int o = 16; o; o >>= 1) x += __shfl_down_sync(0xffffffffu, x, o);
            if (lane == 0) red[wid*4 + v] = x;
        }
        __syncthreads();
        if (tid == 0){
            float tot[4];
            #pragma unroll
            for (int v = 0; v < 4; v++){
                float s = 0.f;
                #pragma unroll
                for (int w = 0; w < 8; w++) s += red[w*4 + v];
                tot[v] = s;
            }
            while (atomicAdd(&g_ctr, 0) < PCB) { }
            __threadfence();
            float cls = 0.f;
            #pragma unroll
            for (int b = 0; b < BATCH; b++){
                float ti = (float)((volatile int*)g_icnt)[b];
                float dn = (float)(((volatile int*)g_pcnt)[b] + ((volatile int*)g_tcnt)[b]);
                cls += (2.f*ti + 1e-6f) / (dn + 1e-6f);
            }

            const float EPS = 1e-6f;
            float TOT = (float)NPIX;
            float s1 = tot[0], s2 = tot[1], n1 = tot[2], sf = tot[3];
            float s_i0 = (TOT - n1) - s2 + s1;
            float card0 = (TOT - s2) + (TOT - n1);
            float card1 = s2 + n1;
            float dice = 1.f - 0.5f * ((2.f*s_i0 + EPS)/(card0 + EPS)
                                     + (2.f*s1 + EPS)/(card1 + EPS));
            float cl = 1.f - cls / (float)BATCH;
            float focal = sf / TOT;
            out[0] = 0.7f*cl + 0.1f*dice + 0.2f*focal;

            #pragma unroll
            for (int b = 0; b < BATCH; b++){
                g_icnt[b] = 0; g_pcnt[b] = 0; g_tcnt[b] = 0;
            }
            __threadfence();
            atomicExch(&g_ctr, 0);
        }
    }
}

// ---------------- launch -----------------------------------------
extern "C" void kernel_launch(void* const* d_in, const int* in_sizes, int n_in,
                              void* d_out, int out_size){
    const float* logits = (const float*)d_in[0];
    const int*   tr     = (const int*)d_in[1];
    kA<<<NBLK, 256>>>(logits, tr);
    kB<<<8*BATCH, 512>>>();
    kCD<<<PCB+1, 256>>>((float*)d_out);
}

// round 14
// speedup vs baseline: 1.1656x; 1.1656x over previous
#include <cuda_runtime.h>
#include <stdint.h>
#include <cooperative_groups.h>
namespace cg = cooperative_groups;

#define BATCH 16
#define WPR 16
#define WPI 8192
#define NPIX 4194304
#define NBLK 2048
#define ROWS_CTA 128
#define NGRP 32
#define SSTRIDE 18
#define SBUF (ROWS_CTA*SSTRIDE)

// ---------------- scratch (no allocation allowed) ----------------
__device__ uint32_t g_pred[BATCH*WPI];
__device__ uint32_t g_true[BATCH*WPI];
__device__ uint32_t g_ps[BATCH*WPI];
__device__ uint32_t g_ts[BATCH*WPI];
__device__ float    g_part[4*NBLK];
__device__ float    g_cl[BATCH];
__device__ int      g_done[BATCH];       // zero-init; reset by last CTA each run

// ---------------- kernel A: binarize + dice/focal partials -------
__global__ __launch_bounds__(256, 7) void kA(const float* __restrict__ logits,
                                             const int*   __restrict__ tr){
    int tid = threadIdx.x;
    int gt  = blockIdx.x*256 + tid;
    int i8  = gt*8;
    int b   = i8 >> 18;
    int rem = i8 & ((1<<18)-1);

    const float4* F = (const float4*)logits;
    size_t q0 = (((size_t)(2*b) << 18) + rem) >> 2;
    size_t q1 = q0 + (1u << 16);
    const int4* T4 = (const int4*)tr;
    size_t qt = ((size_t)i8) >> 2;

    float4 A0 = F[q0], A1 = F[q0+1];
    float4 B0 = F[q1], B1 = F[q1+1];
    int4   t0 = T4[qt], t1 = T4[qt+1];

    float L0[8] = {A0.x,A0.y,A0.z,A0.w,A1.x,A1.y,A1.z,A1.w};
    float L1[8] = {B0.x,B0.y,B0.z,B0.w,B1.x,B1.y,B1.z,B1.w};
    int   TT[8] = {t0.x,t0.y,t0.z,t0.w,t1.x,t1.y,t1.z,t1.w};

    unsigned pm = 0, tm = 0;
    float s1 = 0.f, s2 = 0.f, s3 = 0.f, s4 = 0.f;
    #pragma unroll
    for (int j = 0; j < 8; j++){
        float d = L1[j] - L0[j];
        bool pd = d > 0.f;
        bool tp = TT[j] > 0;
        pm |= (unsigned)pd << j;
        tm |= (unsigned)tp << j;
        float ad = fabsf(d);
        float e  = __expf(-ad);
        float pb = __fdividef(1.f, 1.f + e);
        float lg = -__logf(pb);
        float p1 = pd ? pb : 1.f - pb;
        float ce = (tp == pd) ? lg : (ad + lg);
        float pt = tp ? p1 : 1.f - p1;
        float om = 1.f - pt;
        s4 += 0.25f * om * om * ce;
        s2 += p1;
        s1 += tp ? p1 : 0.f;
        s3 += tp ? 1.f : 0.f;
    }
    ((uint8_t*)g_pred)[gt] = (uint8_t)pm;
    ((uint8_t*)g_true)[gt] = (uint8_t)tm;

    __shared__ float red[8*4];
    int lane = tid & 31, wid = tid >> 5;
    float vals[4] = {s1, s2, s3, s4};
    #pragma unroll
    for (int v = 0; v < 4; v++){
        float x = vals[v];
        #pragma unroll
        for (int o = 16; o; o >>= 1) x += __shfl_down_sync(0xffffffffu, x, o);
        if (lane == 0) red[wid*4 + v] = x;
    }
    __syncthreads();
    if (wid == 0 && lane < 4){
        float s = 0.f;
        #pragma unroll
        for (int w = 0; w < 8; w++) s += red[w*4 + lane];
        g_part[lane*NBLK + blockIdx.x] = s;
    }
}

// ---------------- kernel B: clustered, activity-gated Zhang-Suen -
template<int SUB>
__device__ __forceinline__ void subiter(
    const uint32_t* __restrict__ src, uint32_t* __restrict__ dst,
    const uint32_t* upS, const uint32_t* dnS,
    uint32_t* __restrict__ act,
    const uint32_t* __restrict__ mb_up, const uint32_t* __restrict__ mb_dn,
    uint32_t* up_mbdn, uint32_t* dn_mbup, int mbw,
    int* s_flag_p, int g, int w, uint32_t wm, int tid)
{
    uint32_t am1 = (g == 0)      ? (mb_up[0] | mb_up[1] | mb_up[2])
                                 : (act[g-1] | act[NGRP + g-1]);
    uint32_t a0  = act[g] | act[NGRP + g];
    uint32_t ap1 = (g == NGRP-1) ? (mb_dn[0] | mb_dn[1] | mb_dn[2])
                                 : (act[g+1] | act[NGRP + g+1]);
    uint32_t actv = (am1 | a0 | ap1) & wm;
    __syncthreads();

    bool changed = false;
    if (actv){
        uint32_t C[6], E[6], Wm[6];
        #pragma unroll
        for (int i = 0; i < 6; i++){
            int r = 4*g - 1 + i;
            uint32_t c, l, rr;
            if (r >= 0 && r < ROWS_CTA){
                const uint32_t* row = src + r*SSTRIDE;
                c = row[w]; l = (w > 0) ? row[w-1] : 0u; rr = (w < 15) ? row[w+1] : 0u;
            } else if (r < 0){
                if (upS){
                    const uint32_t* row = upS + (ROWS_CTA-1)*SSTRIDE;
                    c = row[w]; l = (w > 0) ? row[w-1] : 0u; rr = (w < 15) ? row[w+1] : 0u;
                } else { c = l = rr = 0u; }
            } else {
                if (dnS){
                    const uint32_t* row = dnS;
                    c = row[w]; l = (w > 0) ? row[w-1] : 0u; rr = (w < 15) ? row[w+1] : 0u;
                } else { c = l = rr = 0u; }
            }
            C[i]  = c;
            E[i]  = __funnelshift_r(c, rr, 1);
            Wm[i] = __funnelshift_l(l, c, 1);
        }
        #pragma unroll
        for (int k = 0; k < 4; k++){
            int i = k + 1;
            uint32_t cC = C[i];
            uint32_t p2 = C[i-1], p3 = E[i-1], p9 = Wm[i-1];
            uint32_t p4 = E[i],   p8 = Wm[i];
            uint32_t p6 = C[i+1], p5 = E[i+1], p7 = Wm[i+1];

            uint32_t sa = p2 ^ p3 ^ p4, ca = (p2 & p3) | (p4 & (p2 ^ p3));
            uint32_t sb = p5 ^ p6 ^ p7, cb = (p5 & p6) | (p7 & (p5 ^ p6));
            uint32_t sc = p8 ^ p9,      cc = p8 & p9;
            uint32_t S0v = sa ^ sb ^ sc, cd = (sa & sb) | (sc & (sa ^ sb));
            uint32_t t1v = ca ^ cb ^ cc, c1a = (ca & cb) | (cc & (ca ^ cb));
            uint32_t S1v = t1v ^ cd,     c1b = t1v & cd;
            uint32_t S2v = c1a ^ c1b,    S3v = c1a & c1b;
            uint32_t cond1 = (S1v | S2v | S3v) & ~(S3v | (S2v & S1v & S0v));

            uint32_t t0 = ~p2 & p3;
            uint32_t t1_ = ~p3 & p4;
            uint32_t t2 = ~p4 & p5;
            uint32_t t3 = ~p5 & p6;
            uint32_t t4 = ~p6 & p7;
            uint32_t t5 = ~p7 & p8;
            uint32_t t6 = ~p8 & p9;
            uint32_t t7 = ~p9 & p2;
            uint32_t onep = t0, two = 0;
            two |= onep & t1_; onep |= t1_;
            two |= onep & t2;  onep |= t2;
            two |= onep & t3;  onep |= t3;
            two |= onep & t4;  onep |= t4;
            two |= onep & t5;  onep |= t5;
            two |= onep & t6;  onep |= t6;
            two |= onep & t7;  onep |= t7;
            uint32_t condA = onep & ~two;

            uint32_t c3m, c4m;
            if (SUB == 0){ c3m = ~(p2 & p4 & p6); c4m = ~(p4 & p6 & p8); }
            else         { c3m = ~(p2 & p4 & p8); c4m = ~(p2 & p6 & p8); }

            uint32_t remv = cC & cond1 & condA & c3m & c4m;
            dst[(4*g + k)*SSTRIDE + w] = cC & ~remv;
            changed = changed || (remv != 0u);
        }
        if (changed) *s_flag_p = 1;
    }

    unsigned bal = __ballot_sync(0xffffffffu, changed);
    int lane = tid & 31;
    if (lane == 0 || lane == 16){
        uint32_t v = (lane == 0) ? (bal & 0xFFFFu) : (bal >> 16);
        act[SUB*NGRP + g] = v;
        if (g == 0       && up_mbdn) up_mbdn[mbw] = v;
        if (g == NGRP-1  && dn_mbup) dn_mbup[mbw] = v;
    }
}

__global__ void __cluster_dims__(4,1,1) __launch_bounds__(512) kB(){
    __shared__ uint32_t S[2][SBUF];
    __shared__ uint32_t act[2*NGRP];
    __shared__ uint32_t mb_up[3], mb_dn[3];
    __shared__ int s_flag[2];
    __shared__ int s_any;
    __shared__ int s_last;
    __shared__ int redI[16*3];

    cg::cluster_group cl = cg::this_cluster();
    unsigned rank = cl.block_rank();
    int unit = blockIdx.x >> 2;
    int img  = unit >> 1;
    int sel  = unit & 1;
    const uint32_t* srcg = (sel ? g_true : g_pred) + img*WPI + rank*2048;
    uint32_t*       dstg = (sel ? g_ts   : g_ps)   + img*WPI + rank*2048;

    int tid = threadIdx.x;
    int g = tid >> 4, w = tid & 15;

    #pragma unroll
    for (int it = 0; it < 4; it++){
        int idx = tid + it*512;
        S[0][(idx>>4)*SSTRIDE + (idx&15)] = srcg[idx];
    }
    if (tid < NGRP){ act[tid] = 0xFFFFu; act[NGRP + tid] = 0xFFFFu; }
    if (tid == 0){
        uint32_t u = (rank > 0) ? 0xFFFFu : 0u;
        uint32_t d = (rank < 3) ? 0xFFFFu : 0u;
        mb_up[0] = mb_up[1] = mb_up[2] = u;
        mb_dn[0] = mb_dn[1] = mb_dn[2] = d;
        s_flag[0] = 1; s_flag[1] = 1;
    }

    uint32_t* upS    = (rank > 0) ? cl.map_shared_rank(&S[0][0], rank-1) : (uint32_t*)0;
    uint32_t* dnS    = (rank < 3) ? cl.map_shared_rank(&S[0][0], rank+1) : (uint32_t*)0;
    uint32_t* up_mbdn= (rank > 0) ? cl.map_shared_rank(&mb_dn[0], rank-1) : (uint32_t*)0;
    uint32_t* dn_mbup= (rank < 3) ? cl.map_shared_rank(&mb_up[0], rank+1) : (uint32_t*)0;
    int* fp0 = cl.map_shared_rank(&s_flag[0], 0);
    int* fp1 = cl.map_shared_rank(&s_flag[0], 1);
    int* fp2 = cl.map_shared_rank(&s_flag[0], 2);
    int* fp3 = cl.map_shared_rank(&s_flag[0], 3);

    cl.sync();

    uint32_t wm = (w == 0) ? 0x3u : (7u << (w - 1));
    int mbw = 0;
    for (int p = 0; ; p ^= 1){
        if (tid == 0){
            int q = p ^ 1;
            s_any = fp0[q] | fp1[q] | fp2[q] | fp3[q];
            s_flag[p] = 0;
        }
        __syncthreads();
        if (!s_any) break;

        subiter<0>(&S[0][0], &S[1][0],
                   upS, dnS ? dnS : (uint32_t*)0,
                   act, mb_up, mb_dn, up_mbdn, dn_mbup, mbw,
                   &s_flag[p], g, w, wm, tid);
        mbw = (mbw == 2) ? 0 : mbw + 1;
        cl.sync();

        subiter<1>(&S[1][0], &S[0][0],
                   upS ? upS + SBUF : (uint32_t*)0,
                   dnS ? dnS + SBUF : (uint32_t*)0,
                   act, mb_up, mb_dn, up_mbdn, dn_mbup, mbw,
                   &s_flag[p], g, w, wm, tid);
        mbw = (mbw == 2) ? 0 : mbw + 1;
        cl.sync();
    }

    // writeback (unanimous, lock-step exit: no peer smem reads after loop)
    #pragma unroll
    for (int it = 0; it < 4; it++){
        int idx = tid + it*512;
        dstg[idx] = S[0][(idx>>4)*SSTRIDE + (idx&15)];
    }

    // ---- overlapped clDice epilogue: last of 8 CTAs per image ----
    __threadfence();
    __syncthreads();
    if (tid == 0){
        int old = atomicAdd(&g_done[img], 1);
        s_last = (old == 7);
    }
    __syncthreads();
    if (s_last){
        __threadfence();   // acquire: make peer clusters' skeleton writes visible
        const uint4* A  = (const uint4*)(g_ps + img*WPI);
        const uint4* Cc = (const uint4*)(g_ts + img*WPI);
        int inter = 0, sp = 0, st = 0;
        #pragma unroll
        for (int k = 0; k < 4; k++){
            uint4 a = A[tid + k*512], c = Cc[tid + k*512];
            inter += __popc(a.x & c.x) + __popc(a.y & c.y) + __popc(a.z & c.z) + __popc(a.w & c.w);
            sp    += __popc(a.x) + __popc(a.y) + __popc(a.z) + __popc(a.w);
            st    += __popc(c.x) + __popc(c.y) + __popc(c.z) + __popc(c.w);
        }
        int lane = tid & 31, wid = tid >> 5;
        int v3[3] = {inter, sp, st};
        #pragma unroll
        for (int v = 0; v < 3; v++){
            int x = v3[v];
            #pragma unroll
            for (int o = 16; o; o >>= 1) x += __shfl_down_sync(0xffffffffu, x, o);
            if (lane == 0) redI[wid*3 + v] = x;
        }
        __syncthreads();
        if (tid == 0){
            int ti = 0, tp = 0, tt = 0;
            #pragma unroll
            for (int q = 0; q < 16; q++){ ti += redI[q*3]; tp += redI[q*3+1]; tt += redI[q*3+2]; }
            g_cl[img] = (2.f*(float)ti + 1e-6f) / ((float)(tp + tt) + 1e-6f);
            g_done[img] = 0;   // reset for next graph replay
        }
    }
}

// ---------------- kernel D: final combine (stream-ordered) -------
__global__ __launch_bounds__(256) void kD(float* __restrict__ out){
    __shared__ float red[8*4];
    int tid = threadIdx.x;
    int lane = tid & 31, wid = tid >> 5;
    #pragma unroll
    for (int v = 0; v < 4; v++){
        const float4* P = (const float4*)(g_part + v*NBLK);
        float4 a = P[tid], b = P[tid + 256];
        float x = ((a.x + a.y) + (a.z + a.w)) + ((b.x + b.y) + (b.z + b.w));
        #pragma unroll
        for (int o = 16; o; o >>= 1) x += __shfl_down_sync(0xffffffffu, x, o);
        if (lane == 0) red[wid*4 + v] = x;
    }
    __syncthreads();
    if (tid == 0){
        float tot[4];
        #pragma unroll
        for (int v = 0; v < 4; v++){
            float s = 0.f;
            #pragma unroll
            for (int w = 0; w < 8; w++) s += red[w*4 + v];
            tot[v] = s;
        }
        float cls = 0.f;
        #pragma unroll
        for (int b = 0; b < BATCH; b++) cls += g_cl[b];

        const float EPS = 1e-6f;
        float TOT = (float)NPIX;
        float s1 = tot[0], s2 = tot[1], n1 = tot[2], sf = tot[3];
        float s_i0 = (TOT - n1) - s2 + s1;
        float card0 = (TOT - s2) + (TOT - n1);
        float card1 = s2 + n1;
        float dice = 1.f - 0.5f * ((2.f*s_i0 + EPS)/(card0 + EPS)
                                 + (2.f*s1 + EPS)/(card1 + EPS));
        float cl = 1.f - cls / (float)BATCH;
        float focal = sf / TOT;
        out[0] = 0.7f*cl + 0.1f*dice + 0.2f*focal;
    }
}

// ---------------- launch -----------------------------------------
extern "C" void kernel_launch(void* const* d_in, const int* in_sizes, int n_in,
                              void* d_out, int out_size){
    const float* logits = (const float*)d_in[0];
    const int*   tr     = (const int*)d_in[1];
    kA<<<NBLK, 256>>>(logits, tr);
    kB<<<8*BATCH, 512>>>();
    kD<<<1, 256>>>((float*)d_out);
}

// round 17
// speedup vs baseline: 1.1773x; 1.0100x over previous
#include <cuda_runtime.h>
#include <stdint.h>
#include <cooperative_groups.h>
namespace cg = cooperative_groups;

#define BATCH 16
#define WPR 16
#define WPI 8192
#define NPIX 4194304
#define NBLK 2048
#define ROWS_CTA 128
#define NGRP 32
#define SSTRIDE 18
#define SBUF (ROWS_CTA*SSTRIDE)
#define HROWS (ROWS_CTA+2)        // H holds rows -1..128 at index r+1

// ---------------- scratch (no allocation allowed) ----------------
__device__ uint32_t g_pred[BATCH*WPI];
__device__ uint32_t g_true[BATCH*WPI];
__device__ uint32_t g_ps[BATCH*WPI];
__device__ uint32_t g_ts[BATCH*WPI];
__device__ float    g_part[4*NBLK];
__device__ float    g_cl[BATCH];
__device__ int      g_done[BATCH];       // zero-init; reset by last CTA each run

// ---------------- kernel A: binarize + dice/focal partials -------
__global__ __launch_bounds__(256, 7) void kA(const float* __restrict__ logits,
                                             const int*   __restrict__ tr){
    int tid = threadIdx.x;
    int gt  = blockIdx.x*256 + tid;
    int i8  = gt*8;
    int b   = i8 >> 18;
    int rem = i8 & ((1<<18)-1);

    const float4* F = (const float4*)logits;
    size_t q0 = (((size_t)(2*b) << 18) + rem) >> 2;
    size_t q1 = q0 + (1u << 16);
    const int4* T4 = (const int4*)tr;
    size_t qt = ((size_t)i8) >> 2;

    float4 A0 = F[q0], A1 = F[q0+1];
    float4 B0 = F[q1], B1 = F[q1+1];
    int4   t0 = T4[qt], t1 = T4[qt+1];

    float L0[8] = {A0.x,A0.y,A0.z,A0.w,A1.x,A1.y,A1.z,A1.w};
    float L1[8] = {B0.x,B0.y,B0.z,B0.w,B1.x,B1.y,B1.z,B1.w};
    int   TT[8] = {t0.x,t0.y,t0.z,t0.w,t1.x,t1.y,t1.z,t1.w};

    unsigned pm = 0, tm = 0;
    float s1 = 0.f, s2 = 0.f, s3 = 0.f, s4 = 0.f;
    #pragma unroll
    for (int j = 0; j < 8; j++){
        float d = L1[j] - L0[j];
        bool pd = d > 0.f;
        bool tp = TT[j] > 0;
        pm |= (unsigned)pd << j;
        tm |= (unsigned)tp << j;
        float ad = fabsf(d);
        float e  = __expf(-ad);
        float pb = __fdividef(1.f, 1.f + e);
        float lg = -__logf(pb);
        float p1 = pd ? pb : 1.f - pb;
        float ce = (tp == pd) ? lg : (ad + lg);
        float pt = tp ? p1 : 1.f - p1;
        float om = 1.f - pt;
        s4 += 0.25f * om * om * ce;
        s2 += p1;
        s1 += tp ? p1 : 0.f;
        s3 += tp ? 1.f : 0.f;
    }
    ((uint8_t*)g_pred)[gt] = (uint8_t)pm;
    ((uint8_t*)g_true)[gt] = (uint8_t)tm;

    __shared__ float red[8*4];
    int lane = tid & 31, wid = tid >> 5;
    float vals[4] = {s1, s2, s3, s4};
    #pragma unroll
    for (int v = 0; v < 4; v++){
        float x = vals[v];
        #pragma unroll
        for (int o = 16; o; o >>= 1) x += __shfl_down_sync(0xffffffffu, x, o);
        if (lane == 0) red[wid*4 + v] = x;
    }
    __syncthreads();
    if (wid == 0 && lane < 4){
        float s = 0.f;
        #pragma unroll
        for (int w = 0; w < 8; w++) s += red[w*4 + lane];
        g_part[lane*NBLK + blockIdx.x] = s;
    }
}

// ---------------- Zhang-Suen core (bit-parallel, 32 px/word) -----
template<int SUB>
__device__ __forceinline__ uint32_t zs_core(uint32_t cC,
    uint32_t p2,uint32_t p3,uint32_t p4,uint32_t p5,
    uint32_t p6,uint32_t p7,uint32_t p8,uint32_t p9)
{
    uint32_t sa = p2 ^ p3 ^ p4, ca = (p2 & p3) | (p4 & (p2 ^ p3));
    uint32_t sb = p5 ^ p6 ^ p7, cb = (p5 & p6) | (p7 & (p5 ^ p6));
    uint32_t sc = p8 ^ p9,      cc = p8 & p9;
    uint32_t S0v = sa ^ sb ^ sc, cd = (sa & sb) | (sc & (sa ^ sb));
    uint32_t t1v = ca ^ cb ^ cc, c1a = (ca & cb) | (cc & (ca ^ cb));
    uint32_t S1v = t1v ^ cd,     c1b = t1v & cd;
    uint32_t S2v = c1a ^ c1b,    S3v = c1a & c1b;
    uint32_t cond1 = (S1v | S2v | S3v) & ~(S3v | (S2v & S1v & S0v));

    uint32_t t0 = ~p2 & p3, t1 = ~p3 & p4, t2 = ~p4 & p5, t3 = ~p5 & p6;
    uint32_t t4 = ~p6 & p7, t5 = ~p7 & p8, t6 = ~p8 & p9, t7 = ~p9 & p2;
    uint32_t onep = t0, two = 0;
    two |= onep & t1; onep |= t1;
    two |= onep & t2; onep |= t2;
    two |= onep & t3; onep |= t3;
    two |= onep & t4; onep |= t4;
    two |= onep & t5; onep |= t5;
    two |= onep & t6; onep |= t6;
    two |= onep & t7; onep |= t7;
    uint32_t condA = onep & ~two;

    uint32_t c3m, c4m;
    if (SUB == 0){ c3m = ~(p2 & p4 & p6); c4m = ~(p4 & p6 & p8); }
    else         { c3m = ~(p2 & p4 & p8); c4m = ~(p2 & p6 & p8); }
    return cC & cond1 & condA & c3m & c4m;   // removal mask
}

// ---------------- kernel B: private-state Zhang-Suen, 1 sync/iter
__global__ void __cluster_dims__(4,1,1) __launch_bounds__(512) kB(){
    __shared__ uint32_t S[SBUF];                 // state (single buffer)
    __shared__ uint32_t H[HROWS*SSTRIDE];        // sub0 output, rows -1..128
    __shared__ uint32_t mbu[2][2*SSTRIDE];       // [par]: up-peer rows 126,127
    __shared__ uint32_t mbd[2][2*SSTRIDE];       // [par]: dn-peer rows 0,1
    __shared__ uint32_t mbact_up[2], mbact_dn[2];
    __shared__ uint32_t act0[2][NGRP];           // chg_H per parity
    __shared__ uint32_t act1[2][NGRP];           // chg_S per parity
    __shared__ int s_flag[2];
    __shared__ int s_any;
    __shared__ int s_last;
    __shared__ int redI[16*3];

    cg::cluster_group cl = cg::this_cluster();
    unsigned rank = cl.block_rank();
    int unit = blockIdx.x >> 2;
    int img  = unit >> 1;
    int sel  = unit & 1;
    const uint32_t* srcg = (sel ? g_true : g_pred) + img*WPI + rank*2048;
    uint32_t*       dstg = (sel ? g_ts   : g_ps)   + img*WPI + rank*2048;

    int tid = threadIdx.x;
    int g = tid >> 4, w = tid & 15;
    bool hasUp = rank > 0, hasDn = rank < 3;

    #pragma unroll
    for (int it = 0; it < 4; it++){
        int idx = tid + it*512;
        S[(idx>>4)*SSTRIDE + (idx&15)] = srcg[idx];
    }
    if (tid < NGRP){
        act0[0][tid] = 0xFFFFu; act0[1][tid] = 0xFFFFu;
        act1[0][tid] = 0xFFFFu; act1[1][tid] = 0xFFFFu;
    }
    if (tid == 0){
        mbact_up[0] = mbact_up[1] = hasUp ? 0xFFFFu : 0u;
        mbact_dn[0] = mbact_dn[1] = hasDn ? 0xFFFFu : 0u;
        s_flag[0] = 1; s_flag[1] = 1;
    }
    if (!hasUp && tid < SSTRIDE) H[tid] = 0u;                        // row -1 = 0
    if (!hasDn && tid < SSTRIDE) H[(HROWS-1)*SSTRIDE + tid] = 0u;    // row 128 = 0

    // peer push pointers: we are up-peer's DOWN neighbor, etc.
    uint32_t* up_push    = hasUp ? cl.map_shared_rank(&mbd[0][0], rank-1) : (uint32_t*)0;
    uint32_t* dn_push    = hasDn ? cl.map_shared_rank(&mbu[0][0], rank+1) : (uint32_t*)0;
    uint32_t* up_pushact = hasUp ? cl.map_shared_rank(&mbact_dn[0], rank-1) : (uint32_t*)0;
    uint32_t* dn_pushact = hasDn ? cl.map_shared_rank(&mbact_up[0], rank+1) : (uint32_t*)0;
    int* fp0 = cl.map_shared_rank(&s_flag[0], 0);
    int* fp1 = cl.map_shared_rank(&s_flag[0], 1);
    int* fp2 = cl.map_shared_rank(&s_flag[0], 2);
    int* fp3 = cl.map_shared_rank(&s_flag[0], 3);

    __syncthreads();   // S fully loaded before seeding mailboxes
    // seed parity-0 mailboxes with initial boundary rows
    if (tid < 16 && hasUp){
        up_push[tid]           = S[0*SSTRIDE + tid];
        up_push[SSTRIDE + tid] = S[1*SSTRIDE + tid];
    }
    if (tid >= 496 && hasDn){
        int ww = tid - 496;
        dn_push[ww]            = S[126*SSTRIDE + ww];
        dn_push[SSTRIDE + ww]  = S[127*SSTRIDE + ww];
    }
    cl.sync();   // seeds + flags visible cluster-wide

    uint32_t wm = (w == 0) ? 0x3u : (7u << (w - 1));
    int lane = tid & 31;
    uint32_t force = ~0u;         // iter-0 forces sub1 fully active
    int p = 0;
    for (;;){
        if (tid == 0){
            int q = p ^ 1;
            s_any = fp0[q] | fp1[q] | fp2[q] | fp3[q];
            s_flag[p] = 0;
        }
        __syncthreads();
        if (!s_any) break;

        const uint32_t* mu = mbu[p];   // up-peer rows 126,127
        const uint32_t* md = mbd[p];   // dn-peer rows 0,1

        // ===== SUB0: S (+mailbox halo) -> H, exact change tracking =====
        uint32_t actv0;
        {
            uint32_t am1 = (g == 0)      ? mbact_up[p] : act1[p^1][g-1];
            uint32_t a0  = act1[p^1][g];
            uint32_t ap1 = (g == NGRP-1) ? mbact_dn[p] : act1[p^1][g+1];
            actv0 = (am1 | a0 | ap1) & wm;
        }
        bool ch0 = false;
        if (actv0){
            uint32_t C[6], E[6], Wt[6];
            #pragma unroll
            for (int i = 0; i < 6; i++){
                int r = 4*g - 1 + i;
                uint32_t c, l, rr;
                if (r >= 0 && r < ROWS_CTA){
                    const uint32_t* row = S + r*SSTRIDE;
                    c = row[w]; l = (w > 0) ? row[w-1] : 0u; rr = (w < 15) ? row[w+1] : 0u;
                } else if (r < 0){
                    if (hasUp){
                        const uint32_t* row = mu + SSTRIDE;           // row 127
                        c = row[w]; l = (w > 0) ? row[w-1] : 0u; rr = (w < 15) ? row[w+1] : 0u;
                    } else { c = l = rr = 0u; }
                } else {
                    if (hasDn){
                        const uint32_t* row = md;                      // row 128 = peer row 0
                        c = row[w]; l = (w > 0) ? row[w-1] : 0u; rr = (w < 15) ? row[w+1] : 0u;
                    } else { c = l = rr = 0u; }
                }
                C[i]  = c;
                E[i]  = __funnelshift_r(c, rr, 1);
                Wt[i] = __funnelshift_l(l, c, 1);
            }
            #pragma unroll
            for (int k = 0; k < 4; k++){
                int i = k + 1;
                uint32_t remv = zs_core<0>(C[i], C[i-1],E[i-1],E[i],E[i+1],C[i+1],Wt[i+1],Wt[i],Wt[i-1]);
                uint32_t v = C[i] & ~remv;
                uint32_t* hp = H + (4*g + k + 1)*SSTRIDE + w;
                ch0 = ch0 || (v != *hp);
                *hp = v;
            }
            // halo rows, computed locally from 2-deep mailbox data
            if (g == 0 && hasUp){
                uint32_t cN = mu[w],           lN = (w>0)?mu[w-1]:0u,           rN = (w<15)?mu[w+1]:0u;           // row126
                uint32_t cC = mu[SSTRIDE+w],   lC = (w>0)?mu[SSTRIDE+w-1]:0u,   rC = (w<15)?mu[SSTRIDE+w+1]:0u;   // row127
                uint32_t cS = S[w],            lS = (w>0)?S[w-1]:0u,            rS = (w<15)?S[w+1]:0u;            // row0
                uint32_t p2=cN, p6=cS;
                uint32_t p3=__funnelshift_r(cN,rN,1), p9=__funnelshift_l(lN,cN,1);
                uint32_t p4=__funnelshift_r(cC,rC,1), p8=__funnelshift_l(lC,cC,1);
                uint32_t p5=__funnelshift_r(cS,rS,1), p7=__funnelshift_l(lS,cS,1);
                uint32_t v = cC & ~zs_core<0>(cC,p2,p3,p4,p5,p6,p7,p8,p9);
                ch0 = ch0 || (v != H[w]);
                H[w] = v;                                              // H row -1
            }
            if (g == NGRP-1 && hasDn){
                uint32_t cN = S[127*SSTRIDE+w], lN = (w>0)?S[127*SSTRIDE+w-1]:0u, rN = (w<15)?S[127*SSTRIDE+w+1]:0u;
                uint32_t cC = md[w],            lC = (w>0)?md[w-1]:0u,            rC = (w<15)?md[w+1]:0u;           // row128
                uint32_t cS = md[SSTRIDE+w],    lS = (w>0)?md[SSTRIDE+w-1]:0u,    rS = (w<15)?md[SSTRIDE+w+1]:0u;   // row129
                uint32_t p2=cN, p6=cS;
                uint32_t p3=__funnelshift_r(cN,rN,1), p9=__funnelshift_l(lN,cN,1);
                uint32_t p4=__funnelshift_r(cC,rC,1), p8=__funnelshift_l(lC,cC,1);
                uint32_t p5=__funnelshift_r(cS,rS,1), p7=__funnelshift_l(lS,cS,1);
                uint32_t v = cC & ~zs_core<0>(cC,p2,p3,p4,p5,p6,p7,p8,p9);
                uint32_t* hp = H + (HROWS-1)*SSTRIDE + w;
                ch0 = ch0 || (v != *hp);
                *hp = v;                                               // H row 128
            }
        }
        {
            unsigned bal = __ballot_sync(0xffffffffu, ch0);
            if (lane == 0 || lane == 16)
                act0[p][g] = (lane == 0) ? (bal & 0xFFFFu) : (bal >> 16);
        }
        __syncthreads();   // H + act0 complete (local only)

        // ===== SUB1: H -> S in place, exact change tracking =====
        uint32_t actv1;
        {
            uint32_t am1 = (g == 0)      ? act0[p][0]    : act0[p][g-1];
            uint32_t a0  = act0[p][g];
            uint32_t ap1 = (g == NGRP-1) ? act0[p][NGRP-1] : act0[p][g+1];
            actv1 = ((am1 | a0 | ap1) | force) & wm;
        }
        bool ch1 = false;
        if (actv1){
            uint32_t C[6], E[6], Wt[6];
            #pragma unroll
            for (int i = 0; i < 6; i++){
                int r = 4*g - 1 + i;                  // -1..128, all local in H
                const uint32_t* rp = H + (r + 1)*SSTRIDE;
                uint32_t c = rp[w], l = (w>0)?rp[w-1]:0u, rr = (w<15)?rp[w+1]:0u;
                C[i]  = c;
                E[i]  = __funnelshift_r(c, rr, 1);
                Wt[i] = __funnelshift_l(l, c, 1);
            }
            #pragma unroll
            for (int k = 0; k < 4; k++){
                int i = k + 1;
                uint32_t remv = zs_core<1>(C[i], C[i-1],E[i-1],E[i],E[i+1],C[i+1],Wt[i+1],Wt[i],Wt[i-1]);
                uint32_t v = C[i] & ~remv;
                uint32_t* sp = S + (4*g + k)*SSTRIDE + w;
                ch1 = ch1 || (v != *sp);
                *sp = v;
            }
            if (ch1) s_flag[p] = 1;
        }
        {
            unsigned bal = __ballot_sync(0xffffffffu, ch1);
            if (lane == 0 || lane == 16)
                act1[p][g] = (lane == 0) ? (bal & 0xFFFFu) : (bal >> 16);
            // push boundary act flags (parity p^1, read by peer next iter)
            if (tid == 0   && hasUp) up_pushact[p^1] = (bal & 0xFFFFu);
            if (tid == 496 && hasDn) dn_pushact[p^1] = (bal >> 16);
        }
        // push boundary rows unconditionally (each thread re-reads words it owns)
        {
            int base = (p^1)*(2*SSTRIDE);
            if (g == 0 && hasUp){
                up_push[base + w]           = S[0*SSTRIDE + w];
                up_push[base + SSTRIDE + w] = S[1*SSTRIDE + w];
            }
            if (g == NGRP-1 && hasDn){
                dn_push[base + w]           = S[126*SSTRIDE + w];
                dn_push[base + SSTRIDE + w] = S[127*SSTRIDE + w];
            }
        }
        cl.sync();          // ONE cluster sync per iteration
        force = 0u;
        p ^= 1;
    }

    // writeback: S holds converged skeleton; no peer smem touched after loop
    #pragma unroll
    for (int it = 0; it < 4; it++){
        int idx = tid + it*512;
        dstg[idx] = S[(idx>>4)*SSTRIDE + (idx&15)];
    }

    // ---- overlapped clDice epilogue: last of 8 CTAs per image ----
    __threadfence();
    __syncthreads();
    if (tid == 0){
        int old = atomicAdd(&g_done[img], 1);
        s_last = (old == 7);
    }
    __syncthreads();
    if (s_last){
        __threadfence();   // acquire: peer clusters' skeleton writes visible
        const uint4* A  = (const uint4*)(g_ps + img*WPI);
        const uint4* Cc = (const uint4*)(g_ts + img*WPI);
        int inter = 0, sp = 0, st = 0;
        #pragma unroll
        for (int k = 0; k < 4; k++){
            uint4 a = A[tid + k*512], c = Cc[tid + k*512];
            inter += __popc(a.x & c.x) + __popc(a.y & c.y) + __popc(a.z & c.z) + __popc(a.w & c.w);
            sp    += __popc(a.x) + __popc(a.y) + __popc(a.z) + __popc(a.w);
            st    += __popc(c.x) + __popc(c.y) + __popc(c.z) + __popc(c.w);
        }
        int v3[3] = {inter, sp, st};
        #pragma unroll
        for (int v = 0; v < 3; v++){
            int x = v3[v];
            #pragma unroll
            for (int o = 16; o; o >>= 1) x += __shfl_down_sync(0xffffffffu, x, o);
            if (lane == 0) redI[(tid>>5)*3 + v] = x;
        }
        __syncthreads();
        if (tid == 0){
            int ti = 0, tp = 0, tt = 0;
            #pragma unroll
            for (int q = 0; q < 16; q++){ ti += redI[q*3]; tp += redI[q*3+1]; tt += redI[q*3+2]; }
            g_cl[img] = (2.f*(float)ti + 1e-6f) / ((float)(tp + tt) + 1e-6f);
            g_done[img] = 0;   // reset for next graph replay
        }
    }
}

// ---------------- kernel D: final combine (stream-ordered) -------
__global__ __launch_bounds__(256) void kD(float* __restrict__ out){
    __shared__ float red[8*4];
    int tid = threadIdx.x;
    int lane = tid & 31, wid = tid >> 5;
    #pragma unroll
    for (int v = 0; v < 4; v++){
        const float4* P = (const float4*)(g_part + v*NBLK);
        float4 a = P[tid], b = P[tid + 256];
        float x = ((a.x + a.y) + (a.z + a.w)) + ((b.x + b.y) + (b.z + b.w));
        #pragma unroll
        for (int o = 16; o; o >>= 1) x += __shfl_down_sync(0xffffffffu, x, o);
        if (lane == 0) red[wid*4 + v] = x;
    }
    __syncthreads();
    if (tid == 0){
        float tot[4];
        #pragma unroll
        for (int v = 0; v < 4; v++){
            float s = 0.f;
            #pragma unroll
            for (int w = 0; w < 8; w++) s += red[w*4 + v];
            tot[v] = s;
        }
        float cls = 0.f;
        #pragma unroll
        for (int b = 0; b < BATCH; b++) cls += g_cl[b];

        const float EPS = 1e-6f;
        float TOT = (float)NPIX;
        float s1 = tot[0], s2 = tot[1], n1 = tot[2], sf = tot[3];
        float s_i0 = (TOT - n1) - s2 + s1;
        float card0 = (TOT - s2) + (TOT - n1);
        float card1 = s2 + n1;
        float dice = 1.f - 0.5f * ((2.f*s_i0 + EPS)/(card0 + EPS)
                                 + (2.f*s1 + EPS)/(card1 + EPS));
        float cl = 1.f - cls / (float)BATCH;
        float focal = sf / TOT;
        out[0] = 0.7f*cl + 0.1f*dice + 0.2f*focal;
    }
}

// ---------------- launch -----------------------------------------
extern "C" void kernel_launch(void* const* d_in, const int* in_sizes, int n_in,
                              void* d_out, int out_size){
    const float* logits = (const float*)d_in[0];
    const int*   tr     = (const int*)d_in[1];
    kA<<<NBLK, 256>>>(logits, tr);
    kB<<<8*BATCH, 512>>>();
    kD<<<1, 256>>>((float*)d_out);
}